// round 17
// baseline (speedup 1.0000x reference)
#include <cuda_runtime.h>
#include <cuda_bf16.h>
#include <cuda_fp16.h>
#include <cstdint>

// NetG: encoder GRU -> +noise -> decoder GRU -> FC head.
// R17: fp16 asymmetric-split GEMM (A = fp16(h) unsplit; B = Bh + Bl*2^-11,
// Bl pre-scaled x2048, separate accumulator) -> 2 MMA passes instead of 3,
// half the A staging / ldmatrix / h-store traffic. R16 skeleton otherwise:
// R10 counter sync, register-local epilogue, early arrive, 4-deep yp parity.

#define TSZ 256
#define HSZ 256
#define BSZ 512
#define NCTA 256
#define NTHR 128

// smem byte offsets
#define A_OFF 0               // 16 x 512B swizzled fp16 A tile
#define WIHB 8192             // 96 x float4 {w0,w1,w2,bih}  (g*32+c)
#define BHHO 9728             // 96 floats bhh
#define WFCO 10112            // 96 floats wfc (d*32+c)
#define XS   10496            // 16*3 floats x_t
#define SMEM_BYTES 10688

#define BL_SCALE 2048.0f
#define BL_INV   (1.0f / 2048.0f)

__device__ __half g_hbf[2][BSZ * HSZ];            // [buf][b*256+j] fp16 h
__device__ float4 g_yp[4][NCTA][4][16];           // head partials, 4-deep parity
__device__ unsigned g_cnt[32][32];                // [bb][pad] monotonic counter

__device__ __forceinline__ uint32_t smem_u32(const void* p) {
    uint32_t a;
    asm("{ .reg .u64 t; cvta.to.shared.u64 t, %1; cvt.u32.u64 %0, t; }"
        : "=r"(a) : "l"(p));
    return a;
}
__device__ __forceinline__ void ldm4(uint32_t* r, uint32_t addr) {
    asm volatile("ldmatrix.sync.aligned.m8n8.x4.shared.b16 {%0,%1,%2,%3}, [%4];"
        : "=r"(r[0]), "=r"(r[1]), "=r"(r[2]), "=r"(r[3]) : "r"(addr));
}
__device__ __forceinline__ void mma16816(float* c, const uint32_t* a,
                                         uint32_t b0, uint32_t b1) {
    asm volatile(
        "mma.sync.aligned.m16n8k16.row.col.f32.f16.f16.f32 "
        "{%0,%1,%2,%3}, {%4,%5,%6,%7}, {%8,%9}, {%0,%1,%2,%3};"
        : "+f"(c[0]), "+f"(c[1]), "+f"(c[2]), "+f"(c[3])
        : "r"(a[0]), "r"(a[1]), "r"(a[2]), "r"(a[3]), "r"(b0), "r"(b1));
}
__device__ __forceinline__ void arrive(unsigned* cnt) {
    asm volatile("red.add.release.gpu.u32 [%0], 1;" :: "l"(cnt) : "memory");
}
__device__ __forceinline__ void wait_ge(const unsigned* cnt, unsigned target) {
    unsigned v;
    do {
        asm volatile("ld.acquire.gpu.u32 %0, [%1];" : "=r"(v) : "l"(cnt) : "memory");
    } while ((int)(v - target) < 0);
}
__device__ __forceinline__ float sigf(float x) {
    return __fdividef(1.0f, 1.0f + __expf(-x));
}
__device__ __forceinline__ float tanhf_(float x) {
    return 1.0f - __fdividef(2.0f, __expf(2.0f * x) + 1.0f);
}

// Gate-interleaved B fragments (fp16): warp w covers 24 N-rows, full K.
// Bh = fp16(W); Bl = fp16((W - Bh) * 2048) accumulated separately.
__device__ __forceinline__ void stage_Bregs(
    const float* __restrict__ W, uint32_t Bh[3][16][2], uint32_t Bl[3][16][2],
    int ib, int w, int lane)
{
    const int nr = lane >> 2, kc = (lane & 3) * 2;
    const int odd = nr & 1, q2 = nr >> 1;
    #pragma unroll
    for (int nt = 0; nt < 3; ++nt) {
        int idx = nt * 2 + odd;
        int hi3 = (idx >= 3);
        int cl = q2 * 2 + hi3;
        int g = idx - 3 * hi3;
        const float* row = W + (g * HSZ + ib * 32 + w * 8 + cl) * HSZ;
        #pragma unroll
        for (int kt = 0; kt < 16; ++kt) {
            #pragma unroll
            for (int rg = 0; rg < 2; ++rg) {
                int kk = kt * 16 + rg * 8 + kc;
                float2 wv = *(const float2*)(row + kk);
                __half h0 = __float2half(wv.x);
                __half h1 = __float2half(wv.y);
                __half l0 = __float2half((wv.x - __half2float(h0)) * BL_SCALE);
                __half l1 = __float2half((wv.y - __half2float(h1)) * BL_SCALE);
                Bh[nt][kt][rg] = (uint32_t)__half_as_ushort(h0)
                               | ((uint32_t)__half_as_ushort(h1) << 16);
                Bl[nt][kt][rg] = (uint32_t)__half_as_ushort(l0)
                               | ((uint32_t)__half_as_ushort(l1) << 16);
            }
        }
    }
}

extern "C" __global__ void __launch_bounds__(NTHR, 2)
netg_mma(const float* __restrict__ X_p, const float* __restrict__ X_f,
         const float* __restrict__ noise,
         const float* __restrict__ Wih_e, const float* __restrict__ Whh_e,
         const float* __restrict__ bih_e, const float* __restrict__ bhh_e,
         const float* __restrict__ Wih_d, const float* __restrict__ Whh_d,
         const float* __restrict__ bih_d, const float* __restrict__ bhh_d,
         const float* __restrict__ Wfc,   const float* __restrict__ bfc,
         float* __restrict__ out)
{
    extern __shared__ char smc[];
    const uint32_t smb = smem_u32(smc);
    const int tid = threadIdx.x, lane = tid & 31, w = tid >> 5;
    const int bb = blockIdx.x >> 3, ib = blockIdx.x & 7;
    const int rr = lane >> 2, q = lane & 3;

    float4* wihb_s = (float4*)(smc + WIHB);
    float*  bhh_s  = (float*)(smc + BHHO);
    float*  wfc_s  = (float*)(smc + WFCO);
    float*  x_s    = (float*)(smc + XS);
    unsigned* cnt  = &g_cnt[bb][0];

    // ---- weights into registers / params into SMEM (encoder phase) ----
    uint32_t Bh[3][16][2], Bl[3][16][2];
    stage_Bregs(Whh_e, Bh, Bl, ib, w, lane);
    if (tid < 96) {
        int g = tid >> 5, c = tid & 31;
        int row = g * HSZ + ib * 32 + c;
        wihb_s[tid] = make_float4(Wih_e[row * 3], Wih_e[row * 3 + 1],
                                  Wih_e[row * 3 + 2], bih_e[row]);
        bhh_s[tid] = bhh_e[row];
        wfc_s[tid] = Wfc[g * HSZ + ib * 32 + c];
    }

    // this thread's epilogue ownership: batches rr, rr+8; cols lc0, lc0+1
    const int lc0 = w * 8 + q * 2;
    const int bg0 = bb * 16 + rr, bg1 = bg0 + 8;

    // zero h buffer 0 (production index 0)
    *(uint32_t*)(&g_hbf[0][bg0 * HSZ + ib * 32 + lc0]) = 0u;
    *(uint32_t*)(&g_hbf[0][bg1 * HSZ + ib * 32 + lc0]) = 0u;
    float hp[2][2] = {{0.f, 0.f}, {0.f, 0.f}};   // [m(0:rr,1:rr+8)][col]
    __syncthreads();
    if (tid == 0) arrive(cnt);   // init arrival: buffer 0 published

    // ldmatrix per-lane address bases (m16 x k16 via x4)
    const int lgrp = lane >> 3, lrow = lane & 7;
    const int r0 = ((lgrp & 1) << 3) + lrow;
    const int segoff = lgrp >> 1;
    const uint32_t rba = smb + A_OFF + r0 * 512;

    for (int t = 0; t < 2 * TSZ; ++t) {
        const bool enc = t < TSZ;
        const int tt = enc ? t : t - TSZ;

        // stage x_t into SMEM BEFORE the poll
        if (tid < 48) {
            int bl = tid / 3, d = tid - bl * 3;
            float v = 0.f;
            if (enc)          v = X_p[(bb * 16 + bl) * (TSZ * 3) + tt * 3 + d];
            else if (tt > 0)  v = X_f[(bb * 16 + bl) * (TSZ * 3) + (tt - 1) * 3 + d];
            x_s[bl * 3 + d] = v;
        }

        // ---- entry barrier: all 8 producers of this group reached index t ----
        if (tid == 0) wait_ge(cnt, 8u * (unsigned)(t + 1));
        __syncthreads();

        if (t == TSZ) {   // switch to decoder weights
            stage_Bregs(Whh_d, Bh, Bl, ib, w, lane);
            if (tid < 96) {
                int g = tid >> 5, c = tid & 31;
                int row = g * HSZ + ib * 32 + c;
                wihb_s[tid] = make_float4(Wih_d[row * 3], Wih_d[row * 3 + 1],
                                          Wih_d[row * 3 + 2], bih_d[row]);
                bhh_s[tid] = bhh_d[row];
            }
        }

        // ---- stage A (fp16 h): 512 16B-chunks, 4 per thread ----
        {
            const __half* src0 = g_hbf[t & 1] + bb * 16 * HSZ;
            #pragma unroll
            for (int i2 = 0; i2 < 4; ++i2) {
                int idx = tid + i2 * NTHR;
                int mm = idx >> 5, s = idx & 31;
                uint4 v = *(const uint4*)(src0 + mm * HSZ + s * 8);
                *(uint4*)(smc + A_OFF + mm * 512 + ((s ^ (mm & 7)) << 4)) = v;
            }
        }

        // distributed head reduce for decoder tstep tt-2 (yp slot (t-2)&3)
        if (t >= TSZ + 2 && tid < 2) {
            int bl = ib * 2 + tid;
            float s0 = bfc[0], s1 = bfc[1], s2 = bfc[2];
            #pragma unroll
            for (int p = 0; p < 8; ++p)
                #pragma unroll
                for (int ww = 0; ww < 4; ++ww) {
                    float4 v = g_yp[(t - 2) & 3][bb * 8 + p][ww][bl];
                    s0 += v.x; s1 += v.y; s2 += v.z;
                }
            float* po = &out[((bb * 16 + bl) * TSZ + (tt - 2)) * 3];
            po[0] = s0; po[1] = s1; po[2] = s2;
        }
        __syncthreads();

        // ---- tensor-core GEMM: full K per warp, 2 passes (Bh, scaled Bl) ----
        float c1[3][4], c2[3][4];
        #pragma unroll
        for (int nt = 0; nt < 3; ++nt)
            #pragma unroll
            for (int d2 = 0; d2 < 4; ++d2) { c1[nt][d2] = 0.f; c2[nt][d2] = 0.f; }

        #pragma unroll
        for (int kt = 0; kt < 16; ++kt) {
            int seg = kt * 2 + segoff;
            uint32_t so = (uint32_t)((seg ^ lrow) << 4);
            uint32_t a[4];
            ldm4(a, rba + so);
            #pragma unroll
            for (int nt = 0; nt < 3; ++nt) {
                mma16816(c1[nt], a, Bh[nt][kt][0], Bh[nt][kt][1]);
                mma16816(c2[nt], a, Bl[nt][kt][0], Bl[nt][kt][1]);
            }
        }

        // ---- register-local epilogue: combine splits, gates, h update ----
        //  col lc0:   r=c[0][f0], z=c[0][f1], n=c[1][f0]
        //  col lc0+1: r=c[1][f1], z=c[2][f0], n=c[2][f1]
        const bool addn = (t == TSZ - 1);
        float4 wA[2], wB[2];
        float bhr[2], bhz[2], bhn[2];
        #pragma unroll
        for (int cc = 0; cc < 2; ++cc) {
            int lc = lc0 + cc;
            wA[cc] = wihb_s[lc];
            wB[cc] = wihb_s[32 + lc];
            bhr[cc] = bhh_s[lc];
            bhz[cc] = bhh_s[32 + lc];
            bhn[cc] = bhh_s[64 + lc];
        }
        float4 wN0 = wihb_s[64 + lc0], wN1 = wihb_s[64 + lc0 + 1];

        float hnew[2][2];
        #pragma unroll
        for (int mi = 0; mi < 2; ++mi) {
            int bl = rr + mi * 8;
            int f0 = mi * 2, f1 = mi * 2 + 1;
            float x0 = x_s[bl * 3], x1 = x_s[bl * 3 + 1], x2 = x_s[bl * 3 + 2];
            float pr0 = fmaf(c2[0][f0], BL_INV, c1[0][f0]);
            float pz0 = fmaf(c2[0][f1], BL_INV, c1[0][f1]);
            float pn0 = fmaf(c2[1][f0], BL_INV, c1[1][f0]);
            float pr1 = fmaf(c2[1][f1], BL_INV, c1[1][f1]);
            float pz1 = fmaf(c2[2][f0], BL_INV, c1[2][f0]);
            float pn1 = fmaf(c2[2][f1], BL_INV, c1[2][f1]);
            {
                float xr = wA[0].w + wA[0].x * x0 + wA[0].y * x1 + wA[0].z * x2;
                float xz = wB[0].w + wB[0].x * x0 + wB[0].y * x1 + wB[0].z * x2;
                float xn = wN0.w + wN0.x * x0 + wN0.y * x1 + wN0.z * x2;
                float r = sigf(xr + pr0 + bhr[0]);
                float z = sigf(xz + pz0 + bhz[0]);
                float n = tanhf_(xn + r * (pn0 + bhn[0]));
                float h = n + z * (hp[mi][0] - n);
                if (addn) h += noise[(bb * 16 + bl) * HSZ + ib * 32 + lc0];
                hp[mi][0] = h; hnew[mi][0] = h;
            }
            {
                float xr = wA[1].w + wA[1].x * x0 + wA[1].y * x1 + wA[1].z * x2;
                float xz = wB[1].w + wB[1].x * x0 + wB[1].y * x1 + wB[1].z * x2;
                float xn = wN1.w + wN1.x * x0 + wN1.y * x1 + wN1.z * x2;
                float r = sigf(xr + pr1 + bhr[1]);
                float z = sigf(xz + pz1 + bhz[1]);
                float n = tanhf_(xn + r * (pn1 + bhn[1]));
                float h = n + z * (hp[mi][1] - n);
                if (addn) h += noise[(bb * 16 + bl) * HSZ + ib * 32 + lc0 + 1];
                hp[mi][1] = h; hnew[mi][1] = h;
            }
            // fp16 h store (2 cols packed)
            {
                __half h0 = __float2half(hnew[mi][0]);
                __half h1 = __float2half(hnew[mi][1]);
                int off = (bb * 16 + bl) * HSZ + ib * 32 + lc0;
                *(uint32_t*)(&g_hbf[(t + 1) & 1][off]) =
                    (uint32_t)__half_as_ushort(h0)
                    | ((uint32_t)__half_as_ushort(h1) << 16);
            }
        }

        // EARLY publish: h stores complete -> arrive now; head-partial work
        // after, off the inter-CTA critical path. Final step arrives late.
        __syncthreads();
        if (tid == 0 && t != 2 * TSZ - 1) arrive(cnt);

        // fused FC head partial (decoder): per-warp, 2 shfls over q
        if (!enc) {
            #pragma unroll
            for (int mi = 0; mi < 2; ++mi) {
                float y0 = hnew[mi][0] * wfc_s[lc0] + hnew[mi][1] * wfc_s[lc0 + 1];
                float y1 = hnew[mi][0] * wfc_s[32 + lc0] + hnew[mi][1] * wfc_s[32 + lc0 + 1];
                float y2 = hnew[mi][0] * wfc_s[64 + lc0] + hnew[mi][1] * wfc_s[64 + lc0 + 1];
                y0 += __shfl_xor_sync(0xffffffffu, y0, 1);
                y0 += __shfl_xor_sync(0xffffffffu, y0, 2);
                y1 += __shfl_xor_sync(0xffffffffu, y1, 1);
                y1 += __shfl_xor_sync(0xffffffffu, y1, 2);
                y2 += __shfl_xor_sync(0xffffffffu, y2, 1);
                y2 += __shfl_xor_sync(0xffffffffu, y2, 2);
                if (q == 0)
                    g_yp[t & 3][blockIdx.x][w][rr + mi * 8] =
                        make_float4(y0, y1, y2, 0.f);
            }
        }
        if (t == 2 * TSZ - 1) {
            __syncthreads();
            if (tid == 0) arrive(cnt);
        }
    }

    // post-loop: reduce decoder tsteps 254 (yp slot 2) and 255 (slot 3)
    if (tid == 0) wait_ge(cnt, 8u * 513u);
    __syncthreads();
    if (tid < 4) {
        int sel = tid >> 1;
        int bl = ib * 2 + (tid & 1);
        int slot = 2 + sel;
        float s0 = bfc[0], s1 = bfc[1], s2 = bfc[2];
        #pragma unroll
        for (int p = 0; p < 8; ++p)
            #pragma unroll
            for (int ww = 0; ww < 4; ++ww) {
                float4 v = g_yp[slot][bb * 8 + p][ww][bl];
                s0 += v.x; s1 += v.y; s2 += v.z;
            }
        float* po = &out[((bb * 16 + bl) * TSZ + 254 + sel) * 3];
        po[0] = s0; po[1] = s1; po[2] = s2;
    }
    __syncthreads();
    if (tid == 0) arrive(cnt);

    // counter reset for graph replay
    if (ib == 0 && tid == 0) {
        wait_ge(cnt, 8u * 514u);
        asm volatile("st.release.gpu.u32 [%0], %1;" :: "l"(cnt), "r"(0u) : "memory");
    }
}

extern "C" void kernel_launch(void* const* d_in, const int* in_sizes, int n_in,
                              void* d_out, int out_size) {
    const float* X_p   = (const float*)d_in[0];
    const float* X_f   = (const float*)d_in[1];
    const float* noise = (const float*)d_in[2];
    const float* Wih_e = (const float*)d_in[3];
    const float* Whh_e = (const float*)d_in[4];
    const float* bih_e = (const float*)d_in[5];
    const float* bhh_e = (const float*)d_in[6];
    const float* Wih_d = (const float*)d_in[7];
    const float* Whh_d = (const float*)d_in[8];
    const float* bih_d = (const float*)d_in[9];
    const float* bhh_d = (const float*)d_in[10];
    const float* Wfc   = (const float*)d_in[11];
    const float* bfc   = (const float*)d_in[12];
    float* out = (float*)d_out;

    cudaFuncSetAttribute(netg_mma, cudaFuncAttributeMaxDynamicSharedMemorySize,
                         SMEM_BYTES);
    netg_mma<<<NCTA, NTHR, SMEM_BYTES>>>(
        X_p, X_f, noise, Wih_e, Whh_e, bih_e, bhh_e,
        Wih_d, Whh_d, bih_d, bhh_d, Wfc, bfc, out);
}